// round 1
// baseline (speedup 1.0000x reference)
#include <cuda_runtime.h>
#include <cstdint>
#include <cstddef>

#define BB 64
#define LL 1024
#define HH 64
#define LM1 1023

// Scratch (device globals are the allowed scratch mechanism)
__device__ float g_k   [BB * LM1 * HH];   // raw (unnormalized) keys
__device__ float g_v   [BB * LM1 * HH];
__device__ float g_kinv[BB * LM1];        // 1/max(||k||, 1e-12)
__device__ float g_q   [BB * HH];

// Packed f32x2 FMA (Blackwell FFMA2 path; PTX fma.rn.f32x2)
__device__ __forceinline__ float2 fma2(float2 a, float2 b, float2 c) {
    float2 d;
    asm("fma.rn.f32x2 %0, %1, %2, %3;"
        : "=l"(*reinterpret_cast<unsigned long long*>(&d))
        : "l"(*reinterpret_cast<unsigned long long*>(&a)),
          "l"(*reinterpret_cast<unsigned long long*>(&b)),
          "l"(*reinterpret_cast<unsigned long long*>(&c)));
    return d;
}

// ---------------------------------------------------------------------------
// Kernel 1: per-token embed -> FF -> residual -> LayerNorm -> k/v/q proj.
// One thread per token; weights transposed in dynamic shared memory.
// ---------------------------------------------------------------------------
__global__ __launch_bounds__(256, 1)
void k_tokens(const int*   __restrict__ seq,
              const float* __restrict__ embedW,
              const float* __restrict__ W1,   // [64][128]
              const float* __restrict__ b1,   // [128]
              const float* __restrict__ W2,   // [128][64]
              const float* __restrict__ b2,   // [64]
              const float* __restrict__ lng,
              const float* __restrict__ lnb,
              const float* __restrict__ kpW,  // [64][64]
              const float* __restrict__ vpW,
              const float* __restrict__ qpW)
{
    extern __shared__ float sm[];
    float* sW1t = sm;             // [128][64]  (transposed W1)
    float* sW2  = sm + 8192;      // [128][64]  (as-is)
    float* sKpT = sm + 16384;     // [64][64]   (transposed)
    float* sVpT = sm + 20480;
    float* sQpT = sm + 24576;
    float* sB1  = sm + 28672;     // 128
    float* sB2  = sm + 28800;     // 64
    float* sG   = sm + 28864;     // 64
    float* sBt  = sm + 28928;     // 64

    const int tid = threadIdx.x;
    for (int idx = tid; idx < 8192; idx += 256) {
        int i = idx >> 7, j = idx & 127;      // W1[i][j]
        sW1t[j * 64 + i] = W1[idx];
    }
    for (int idx = tid; idx < 8192; idx += 256) sW2[idx] = W2[idx];
    for (int idx = tid; idx < 4096; idx += 256) {
        int i = idx >> 6, c = idx & 63;
        sKpT[c * 64 + i] = kpW[idx];
        sVpT[c * 64 + i] = vpW[idx];
        sQpT[c * 64 + i] = qpW[idx];
    }
    if (tid < 128) sB1[tid] = b1[tid];
    if (tid < 64) { sB2[tid] = b2[tid]; sG[tid] = lng[tid]; sBt[tid] = lnb[tid]; }
    __syncthreads();

    const int token = blockIdx.x * 256 + tid;
    const int b = token >> 10;
    const int t = token & 1023;
    const int sidx = seq[token];

    float2 h2[32];
    {
        const float4* e4 = reinterpret_cast<const float4*>(embedW + (sidx << 6));
        #pragma unroll
        for (int k = 0; k < 16; k++) {
            float4 w = e4[k];
            h2[2 * k]     = make_float2(w.x, w.y);
            h2[2 * k + 1] = make_float2(w.z, w.w);
        }
    }

    // FF: stream over hidden j, accumulate ff2 in acc
    float2 acc[32];
    #pragma unroll
    for (int k = 0; k < 32; k++) acc[k] = make_float2(sB2[2 * k], sB2[2 * k + 1]);

    for (int j = 0; j < 128; j++) {
        const float4* w1 = reinterpret_cast<const float4*>(sW1t + (j << 6));
        float2 p0 = make_float2(0.f, 0.f), p1 = p0, p2 = p0, p3 = p0;
        #pragma unroll
        for (int k = 0; k < 16; k += 2) {
            float4 wa = w1[k];
            float4 wb = w1[k + 1];
            p0 = fma2(h2[2 * k],     make_float2(wa.x, wa.y), p0);
            p1 = fma2(h2[2 * k + 1], make_float2(wa.z, wa.w), p1);
            p2 = fma2(h2[2 * k + 2], make_float2(wb.x, wb.y), p2);
            p3 = fma2(h2[2 * k + 3], make_float2(wb.z, wb.w), p3);
        }
        float sj = ((p0.x + p0.y) + (p1.x + p1.y)) + ((p2.x + p2.y) + (p3.x + p3.y)) + sB1[j];
        sj = fmaxf(sj, 0.0f);
        float2 s2 = make_float2(sj, sj);
        const float4* w2 = reinterpret_cast<const float4*>(sW2 + (j << 6));
        #pragma unroll
        for (int k = 0; k < 16; k++) {
            float4 w = w2[k];
            acc[2 * k]     = fma2(s2, make_float2(w.x, w.y), acc[2 * k]);
            acc[2 * k + 1] = fma2(s2, make_float2(w.z, w.w), acc[2 * k + 1]);
        }
    }

    // x = h + ff; LayerNorm (whole token in-thread: no cross-thread reductions)
    #pragma unroll
    for (int k = 0; k < 32; k++) { h2[k].x += acc[k].x; h2[k].y += acc[k].y; }
    float2 s = make_float2(0.f, 0.f);
    #pragma unroll
    for (int k = 0; k < 32; k++) { s.x += h2[k].x; s.y += h2[k].y; }
    const float mu = (s.x + s.y) * (1.0f / 64.0f);
    float2 vs = make_float2(0.f, 0.f);
    #pragma unroll
    for (int k = 0; k < 32; k++) {
        float dx = h2[k].x - mu, dy = h2[k].y - mu;
        vs.x += dx * dx; vs.y += dy * dy;
    }
    const float var = (vs.x + vs.y) * (1.0f / 64.0f);
    const float inv = 1.0f / sqrtf(var + 1e-5f);
    #pragma unroll
    for (int k = 0; k < 32; k++) {
        h2[k].x = (h2[k].x - mu) * inv * sG[2 * k]     + sBt[2 * k];
        h2[k].y = (h2[k].y - mu) * inv * sG[2 * k + 1] + sBt[2 * k + 1];
    }

    auto dot64 = [&](const float* wt) -> float {
        const float4* w4 = reinterpret_cast<const float4*>(wt);
        float2 p0 = make_float2(0.f, 0.f), p1 = p0, p2 = p0, p3 = p0;
        #pragma unroll
        for (int k = 0; k < 16; k += 2) {
            float4 wa = w4[k];
            float4 wb = w4[k + 1];
            p0 = fma2(h2[2 * k],     make_float2(wa.x, wa.y), p0);
            p1 = fma2(h2[2 * k + 1], make_float2(wa.z, wa.w), p1);
            p2 = fma2(h2[2 * k + 2], make_float2(wb.x, wb.y), p2);
            p3 = fma2(h2[2 * k + 3], make_float2(wb.z, wb.w), p3);
        }
        return ((p0.x + p0.y) + (p1.x + p1.y)) + ((p2.x + p2.y) + (p3.x + p3.y));
    };

    if (t < LM1) {
        const size_t base = ((size_t)(b * LM1 + t)) << 6;
        float nk = 0.f;
        for (int c = 0; c < 64; c += 4) {
            float4 o;
            o.x = dot64(sKpT + (c << 6));
            o.y = dot64(sKpT + ((c + 1) << 6));
            o.z = dot64(sKpT + ((c + 2) << 6));
            o.w = dot64(sKpT + ((c + 3) << 6));
            nk += o.x * o.x + o.y * o.y + o.z * o.z + o.w * o.w;
            *reinterpret_cast<float4*>(g_k + base + c) = o;
        }
        g_kinv[b * LM1 + t] = 1.0f / fmaxf(sqrtf(nk), 1e-12f);
        for (int c = 0; c < 64; c += 4) {
            float4 o;
            o.x = dot64(sVpT + (c << 6));
            o.y = dot64(sVpT + ((c + 1) << 6));
            o.z = dot64(sVpT + ((c + 2) << 6));
            o.w = dot64(sVpT + ((c + 3) << 6));
            *reinterpret_cast<float4*>(g_v + base + c) = o;
        }
    } else {
        for (int c = 0; c < 64; c += 4) {
            float4 o;
            o.x = dot64(sQpT + (c << 6));
            o.y = dot64(sQpT + ((c + 1) << 6));
            o.z = dot64(sQpT + ((c + 2) << 6));
            o.w = dot64(sQpT + ((c + 3) << 6));
            *reinterpret_cast<float4*>(g_q + (b << 6) + c) = o;
        }
    }
}

// ---------------------------------------------------------------------------
// Kernel 2: sequential gated fast-weight scan + epilogue.
// One CTA per batch, 64 threads; thread i owns M row i (32 x float2 regs).
// ---------------------------------------------------------------------------
__global__ __launch_bounds__(64, 1)
void k_scan(const float* __restrict__ rpW,
            const float* __restrict__ rpb,
            const float* __restrict__ outW,
            const float* __restrict__ outb,
            float* __restrict__ out)
{
    __shared__ float skn[2][64];
    __shared__ float sred[2];
    __shared__ float sv[64];

    const int i = threadIdx.x;
    const int b = blockIdx.x;
    const int lane = i & 31, w = i >> 5;

    float2 M[32];
    #pragma unroll
    for (int k = 0; k < 32; k++) M[k] = make_float2(0.f, 0.f);

    const size_t base = (size_t)b * LM1 * 64;
    float kraw = g_k[base + i];
    float vcur = g_v[base + i];
    float kinv = g_kinv[b * LM1];

    for (int t = 0; t < LM1; t++) {
        const int pb = t & 1;
        skn[pb][i] = kraw * kinv;

        // prefetch next step (L2-resident; hides ~250cyc behind the step)
        float knext = 0.f, vnext = 0.f, kinvn = 0.f;
        if (t + 1 < LM1) {
            knext = g_k[base + (size_t)(t + 1) * 64 + i];
            vnext = g_v[base + (size_t)(t + 1) * 64 + i];
            kinvn = g_kinv[b * LM1 + t + 1];
        }
        __syncthreads();

        // snapshot kn into registers (used by matvec AND update)
        float4 kr[16];
        {
            const float4* k4 = reinterpret_cast<const float4*>(skn[pb]);
            #pragma unroll
            for (int k = 0; k < 16; k++) kr[k] = k4[k];
        }

        // vp_i = M[i,:] . kn
        float2 p0 = make_float2(0.f, 0.f), p1 = p0, p2 = p0, p3 = p0;
        #pragma unroll
        for (int k = 0; k < 16; k += 2) {
            p0 = fma2(M[2 * k],     make_float2(kr[k].x,     kr[k].y),     p0);
            p1 = fma2(M[2 * k + 1], make_float2(kr[k].z,     kr[k].w),     p1);
            p2 = fma2(M[2 * k + 2], make_float2(kr[k + 1].x, kr[k + 1].y), p2);
            p3 = fma2(M[2 * k + 3], make_float2(kr[k + 1].z, kr[k + 1].w), p3);
        }
        const float vp = ((p0.x + p0.y) + (p1.x + p1.y)) + ((p2.x + p2.y) + (p3.x + p3.y));
        const float d = vcur - vp;

        // single fused reduction: sum(d^2) - 0.16*sum(v^2) > 0  <=>  err > 0.4*||v||
        float z = d * d - 0.16f * vcur * vcur;
        #pragma unroll
        for (int o = 16; o > 0; o >>= 1) z += __shfl_xor_sync(0xffffffffu, z, o);
        if (lane == 0) sred[w] = z;
        __syncthreads();
        const float zt = sred[0] + sred[1];

        if (zt > 0.0f) {   // uniform across CTA
            float2 d2 = make_float2(d, d);
            #pragma unroll
            for (int k = 0; k < 16; k++) {
                M[2 * k]     = fma2(d2, make_float2(kr[k].x, kr[k].y), M[2 * k]);
                M[2 * k + 1] = fma2(d2, make_float2(kr[k].z, kr[k].w), M[2 * k + 1]);
            }
        }
        kraw = knext; vcur = vnext; kinv = kinvn;
    }

    // -------- epilogue: r = (M q) @ rp_W + rp_b ; out = r @ out_W + out_b ---
    __syncthreads();
    skn[0][i] = g_q[(b << 6) + i];
    __syncthreads();
    float mq;
    {
        const float4* k4 = reinterpret_cast<const float4*>(skn[0]);
        float2 p0 = make_float2(0.f, 0.f), p1 = p0, p2 = p0, p3 = p0;
        #pragma unroll
        for (int k = 0; k < 16; k += 2) {
            float4 wa = k4[k];
            float4 wb = k4[k + 1];
            p0 = fma2(M[2 * k],     make_float2(wa.x, wa.y), p0);
            p1 = fma2(M[2 * k + 1], make_float2(wa.z, wa.w), p1);
            p2 = fma2(M[2 * k + 2], make_float2(wb.x, wb.y), p2);
            p3 = fma2(M[2 * k + 3], make_float2(wb.z, wb.w), p3);
        }
        mq = ((p0.x + p0.y) + (p1.x + p1.y)) + ((p2.x + p2.y) + (p3.x + p3.y));
    }
    __syncthreads();
    sv[i] = mq;
    __syncthreads();
    float r = rpb[i];
    for (int j = 0; j < 64; j++) r = fmaf(sv[j], rpW[j * 64 + i], r);
    __syncthreads();
    sv[i] = r;
    __syncthreads();
    float o = outb[i];
    for (int j = 0; j < 64; j++) o = fmaf(sv[j], outW[j * 64 + i], o);
    out[(b << 6) + i] = o;
}

// ---------------------------------------------------------------------------
extern "C" void kernel_launch(void* const* d_in, const int* in_sizes, int n_in,
                              void* d_out, int out_size)
{
    const int*   seq    = (const int*)  d_in[0];
    const float* embedW = (const float*)d_in[1];
    const float* W1     = (const float*)d_in[2];
    const float* b1     = (const float*)d_in[3];
    const float* W2     = (const float*)d_in[4];
    const float* b2     = (const float*)d_in[5];
    const float* lng    = (const float*)d_in[6];
    const float* lnb    = (const float*)d_in[7];
    const float* kpW    = (const float*)d_in[8];
    const float* vpW    = (const float*)d_in[9];
    const float* qpW    = (const float*)d_in[10];
    const float* rpW    = (const float*)d_in[11];
    const float* rpb    = (const float*)d_in[12];
    const float* outW   = (const float*)d_in[13];
    const float* outb   = (const float*)d_in[14];
    float* out = (float*)d_out;

    const int smem = 28992 * (int)sizeof(float);   // 115968 B
    cudaFuncSetAttribute(k_tokens, cudaFuncAttributeMaxDynamicSharedMemorySize, smem);

    k_tokens<<<256, 256, smem>>>(seq, embedW, W1, b1, W2, b2, lng, lnb, kpW, vpW, qpW);
    k_scan<<<64, 64>>>(rpW, rpb, outW, outb, out);
}